// round 6
// baseline (speedup 1.0000x reference)
#include <cuda_runtime.h>
#include <stdint.h>

#define B_    512
#define T_    76
#define HIST  10
#define H_    256
#define NSTEP 64
#define MLPH  15000
#define K1    130
#define NCH2  469
#define CHF   (NCH2 * 2048)   // 960512 floats per 64-row strip

__device__ __align__(16) float g_mlpf[8][CHF];
__device__ __align__(16) float g_W2f[(size_t)64 * CHF];
__device__ __align__(16) float g_h[2][8][8][16384];
__device__ __align__(16) float g_h7row[8][64][256];
__device__ __align__(16) float g_c[8][B_][H_];
__device__ __align__(16) float g_Wp[4194304];      // [l][bh][s][kc][2048]  s:0=Whh,1=Wih
__device__ __align__(16) float g_Wih0p[16][1024];
__device__ unsigned g_prog[128];

__device__ __forceinline__ float tf32f(float x) {
    uint32_t r; asm("cvt.rna.tf32.f32 %0, %1;" : "=r"(r) : "f"(x));
    return __uint_as_float(r);
}
#define U(x) __float_as_uint(x)
__device__ __forceinline__ void mma8(float c[4], uint32_t a0, uint32_t a1, uint32_t a2, uint32_t a3,
                                     uint32_t b0, uint32_t b1) {
    asm volatile("mma.sync.aligned.m16n8k8.row.col.f32.tf32.tf32.f32 "
                 "{%0,%1,%2,%3},{%4,%5,%6,%7},{%8,%9},{%0,%1,%2,%3};\n"
                 : "+f"(c[0]), "+f"(c[1]), "+f"(c[2]), "+f"(c[3])
                 : "r"(a0), "r"(a1), "r"(a2), "r"(a3), "r"(b0), "r"(b1));
}
__device__ __forceinline__ float sigf(float x) { return __fdividef(1.f, 1.f + __expf(-x)); }
__device__ __forceinline__ float tanhf_(float x) { return 2.f * sigf(2.f * x) - 1.f; }
__device__ __forceinline__ void cpa16(void* s, const void* g) {
    uint32_t sa = (uint32_t)__cvta_generic_to_shared(s);
    asm volatile("cp.async.cg.shared.global [%0], [%1], 16;" :: "r"(sa), "l"(g));
}
#define CP_COMMIT() asm volatile("cp.async.commit_group;\n")
#define CP_WAIT(n)  asm volatile("cp.async.wait_group %0;\n" :: "n"(n))

// fragment offset of (r,k) in a 64-row x (32*nchunk)-k tile (k<256 ok)
__device__ __forceinline__ int hfrag(int r, int k) {
    return ((((k >> 3) * 4 + (r >> 4)) * 32 + (r & 7) * 4 + (k & 3)) << 2)
           + ((r >> 3) & 1) + (((k >> 2) & 1) << 1);
}

__device__ __forceinline__ void mma_frag(const float4* Ac, const float4* Bc,
                                         float (&acc)[4][4], int wm, int wn, int lane) {
#pragma unroll
    for (int k8 = 0; k8 < 4; k8++) {
        float4 a  = Ac[(k8 * 4 + wm) * 32 + lane];
        float4 b0 = Bc[((k8 * 2 + wn) * 2 + 0) * 32 + lane];
        float4 b1 = Bc[((k8 * 2 + wn) * 2 + 1) * 32 + lane];
        mma8(acc[0], U(a.x), U(a.y), U(a.z), U(a.w), U(b0.x), U(b0.y));
        mma8(acc[1], U(a.x), U(a.y), U(a.z), U(a.w), U(b0.z), U(b0.w));
        mma8(acc[2], U(a.x), U(a.y), U(a.z), U(a.w), U(b1.x), U(b1.y));
        mma8(acc[3], U(a.x), U(a.y), U(a.z), U(a.w), U(b1.z), U(b1.w));
    }
}

// ---- prep: rollout weights, gate-interleaved, [l][bh][s][kc] ----
__global__ void __launch_bounds__(256) k_prep_w(const float* __restrict__ Whh0,
                                                const float* __restrict__ Wih,
                                                const float* __restrict__ Whh) {
    const int idx = blockIdx.x * 256 + threadIdx.x;
    const int comp = idx & 3, c4 = (idx >> 2) & 511;
    const int lane = c4 & 31, half = (c4 >> 5) & 1, wn = (c4 >> 6) & 1, k8 = (c4 >> 7) & 3;
    const int kc = (idx >> 11) & 7, s = (idx >> 14) & 1, bh = (idx >> 15) & 15, l = (idx >> 19) & 7;
    const int gc = (wn * 4 + half * 2 + (comp >> 1)) * 8 + (lane >> 2);
    const int n = ((gc >> 3) & 3) * 256 + bh * 16 + (gc >> 5) * 8 + (gc & 7);
    const int k = kc * 32 + k8 * 8 + (comp & 1) * 4 + (lane & 3);
    float v = 0.f;
    if (l == 0) { if (s == 0) v = Whh0[n * 256 + k]; }
    else v = (s == 0) ? Whh[(size_t)(l - 1) * 262144 + n * 256 + k]
                      : Wih[(size_t)(l - 1) * 262144 + n * 256 + k];
    g_Wp[idx] = tf32f(v);
}

// ---- prep: W2 fragments (plain column order) ----
__global__ void __launch_bounds__(256) k_prep_w2(const float* __restrict__ W2) {
    const size_t i4 = (size_t)blockIdx.x * 256 + threadIdx.x;
    const int lane = (int)(i4 & 31), half = (int)((i4 >> 5) & 1);
    const int wn = (int)((i4 >> 6) & 1), k8 = (int)((i4 >> 7) & 3);
    const int ch = (int)(i4 >> 9);
    const int bn = ch / NCH2, kc = ch - bn * NCH2;
    float4 v; float* pv = (float*)&v;
#pragma unroll
    for (int c = 0; c < 4; c++) {
        const int gc = (wn * 4 + half * 2 + (c >> 1)) * 8 + (lane >> 2);
        const int n = bn * 64 + gc;
        const int k = kc * 32 + k8 * 8 + (c & 1) * 4 + (lane & 3);
        pv[c] = (k < MLPH) ? tf32f(W2[(size_t)n * MLPH + k]) : 0.f;
    }
    ((float4*)g_W2f)[i4] = v;
}

__global__ void __launch_bounds__(256) k_prep_small(const float* __restrict__ Wih0) {
    const int i = blockIdx.x * 256 + threadIdx.x;
    if (i < 16384) {
        const int bh = i >> 10, pos = i & 1023;
        const int comp = pos & 3, c4 = pos >> 2;
        const int lane = c4 & 31, half = (c4 >> 5) & 1, wn = (c4 >> 6) & 1, k8 = (c4 >> 7) & 1;
        const int gc = (wn * 4 + half * 2 + (comp >> 1)) * 8 + (lane >> 2);
        const int n = ((gc >> 3) & 3) * 256 + bh * 16 + (gc >> 5) * 8 + (gc & 7);
        const int k = k8 * 8 + (comp & 1) * 4 + (lane & 3);
        g_Wih0p[bh][pos] = (k < 14) ? tf32f(Wih0[n * 14 + k]) : 0.f;
    } else if (i < 16384 + 4096) {
        const int j = i - 16384;
        const int rg = j >> 9, rem = j & 511;
        g_mlpf[rg][468 * 2048 + hfrag(rem >> 3, 24 + (rem & 7))] = 0.f;
    } else if (i < 16384 + 4096 + 128) {
        g_prog[i - 16384 - 4096] = 0u;
    }
}

// ---- GEMM1 (fp32 FFMA) -> fragment-ordered mlp ----
__global__ void __launch_bounds__(256) k_gemm1(const float* __restrict__ states,
                                               const float* __restrict__ acts,
                                               const float* __restrict__ W1,
                                               const float* __restrict__ b1) {
    const int bm = blockIdx.x & 15, bn = blockIdx.x >> 4, n0 = bn * 128;
    const int tid = threadIdx.x;
    __shared__ float enc_s[32][132];
    __shared__ float w_s[128][33];
    for (int i = tid; i < 32 * K1; i += 256) {
        const int r = i / K1, k = i % K1, b = bm * 32 + r;
        const int tt = k / 13, j = k % 13;
        enc_s[r][k] = (j < 9) ? states[(b * T_ + tt) * 12 + 3 + j]
                              : acts[(b * T_ + tt) * 4 + (j - 9)];
    }
    float acc[4][4];
#pragma unroll
    for (int a = 0; a < 4; a++)
#pragma unroll
        for (int b = 0; b < 4; b++) acc[a][b] = 0.f;
    const int tr = tid >> 5, tc = tid & 31;
    for (int k0 = 0; k0 < K1; k0 += 32) {
        const int kn = min(32, K1 - k0);
        __syncthreads();
        for (int i = tid; i < 4096; i += 256) {
            const int c = i >> 5, kk = i & 31, n = n0 + c;
            w_s[c][kk] = (kk < kn && n < MLPH) ? W1[n * K1 + k0 + kk] : 0.f;
        }
        __syncthreads();
        for (int kk = 0; kk < kn; kk++) {
            float a[4], w[4];
#pragma unroll
            for (int x = 0; x < 4; x++) a[x] = enc_s[tr + 8 * x][k0 + kk];
#pragma unroll
            for (int y = 0; y < 4; y++) w[y] = w_s[tc + 32 * y][kk];
#pragma unroll
            for (int x = 0; x < 4; x++)
#pragma unroll
                for (int y = 0; y < 4; y++) acc[x][y] += a[x] * w[y];
        }
    }
#pragma unroll
    for (int x = 0; x < 4; x++)
#pragma unroll
        for (int y = 0; y < 4; y++) {
            const int b = bm * 32 + tr + 8 * x, n = n0 + tc + 32 * y;
            if (n < MLPH)
                g_mlpf[b >> 6][(n >> 5) * 2048 + hfrag(b & 63, n & 31)] =
                    tf32f(fmaxf(acc[x][y] + b1[n], 0.f));
        }
}

// ---- GEMM2: fragment pipeline ----
__global__ void __launch_bounds__(256, 2) k_gemm2(const float* __restrict__ b2) {
    const int bm = blockIdx.x & 7, bn = blockIdx.x >> 3;
    const int tid = threadIdx.x;
    const int warp = tid >> 5, lane = tid & 31;
    const int wm = warp >> 1, wn = warp & 1;
    const int g = lane >> 2, tq = lane & 3;
    extern __shared__ __align__(16) float4 s4[];
    float4* A4 = s4; float4* B4 = s4 + 3 * 512;
    const float4* Asrc = (const float4*)g_mlpf[bm];
    const float4* Bsrc = ((const float4*)g_W2f) + (size_t)bn * (NCH2 * 512);

    float acc[4][4];
#pragma unroll
    for (int j = 0; j < 4; j++)
#pragma unroll
        for (int d = 0; d < 4; d++) acc[j][d] = 0.f;

    auto stage = [&](int s, int c) {
        cpa16(&A4[s * 512 + tid], Asrc + (size_t)c * 512 + tid);
        cpa16(&A4[s * 512 + tid + 256], Asrc + (size_t)c * 512 + tid + 256);
        cpa16(&B4[s * 512 + tid], Bsrc + (size_t)c * 512 + tid);
        cpa16(&B4[s * 512 + tid + 256], Bsrc + (size_t)c * 512 + tid + 256);
        CP_COMMIT();
    };
    stage(0, 0); stage(1, 1);
    for (int c = 0; c < NCH2; c++) {
        if (c < NCH2 - 1) CP_WAIT(1); else CP_WAIT(0);
        __syncthreads();
        if (c + 2 < NCH2) stage((c + 2) % 3, c + 2);
        mma_frag(A4 + (c % 3) * 512, B4 + (c % 3) * 512, acc, wm, wn, lane);
    }
#pragma unroll
    for (int j = 0; j < 4; j++)
#pragma unroll
        for (int d = 0; d < 4; d++) {
            const int r = wm * 16 + g + ((d & 2) ? 8 : 0);
            const int p = (wn * 4 + j) * 8 + tq * 2 + (d & 1);
            const int n = bn * 64 + p;
            const float v = acc[j][d] + b2[n];
            const int l = n >> 9, rem = n & 511;
            if (rem < H_) g_h[1][l][bm][hfrag(r, rem)] = tf32f(v);
            else          g_c[l][bm * 64 + r][rem - H_] = v;
        }
}

// ---- rollout ----
__global__ void __launch_bounds__(256) k_rollout(
    const float* __restrict__ states, const float* __restrict__ acts,
    const float* __restrict__ dts,
    const float* __restrict__ bih0, const float* __restrict__ bhh0,
    const float* __restrict__ bih, const float* __restrict__ bhh,
    const float* __restrict__ Wfc, const float* __restrict__ bfc,
    float* __restrict__ out)
{
    const int rg = blockIdx.x >> 4, bh = blockIdx.x & 15;
    const int tid = threadIdx.x;
    const int warp = tid >> 5, lane = tid & 31;
    const int wm = warp >> 1, wn = warp & 1;
    const int g = lane >> 2, tq = lane & 3;
    const int row0 = rg * 64, hc0 = bh * 16;

    extern __shared__ __align__(16) float sm[];
    float4* A4 = (float4*)sm;
    float4* B4 = (float4*)(sm + 6144);
    float4* AX = (float4*)(sm + 12288);
    float4* BX = (float4*)(sm + 13312);
    float (*Gs)[68]   = (float(*)[68])(sm + 14336);
    float (*xs)[16]   = (float(*)[16])(sm + 18688);
    float (*bias)[64] = (float(*)[64])(sm + 19712);

    cpa16(&BX[tid], &((const float4*)g_Wih0p[bh])[tid]);
    CP_COMMIT();

    for (int i = tid; i < 512; i += 256) {
        const int l = i >> 6, gc = i & 63;
        const int n = (gc >> 4) * 256 + hc0 + (gc & 15);
        bias[l][gc] = (l == 0) ? __ldg(&bih0[n]) + __ldg(&bhh0[n])
                               : __ldg(&bih[(l - 1) * 1024 + n]) + __ldg(&bhh[(l - 1) * 1024 + n]);
    }
    float c_reg[8][4];
#pragma unroll
    for (int l = 0; l < 8; l++)
#pragma unroll
        for (int d = 0; d < 4; d++) {
            const int r = wm * 16 + g + ((d & 2) ? 8 : 0);
            const int hc = wn * 8 + tq * 2 + (d & 1);
            c_reg[l][d] = __ldcg(&g_c[l][row0 + r][hc0 + hc]);
        }
    for (int i = tid; i < 576; i += 256) {
        const int r = i / 9, j = i % 9;
        xs[r][1 + j] = states[((row0 + r) * T_ + HIST) * 12 + 3 + j];
    }
    if (tid < 128) xs[tid >> 1][14 + (tid & 1)] = 0.f;
    CP_WAIT(0);
    __syncthreads();

    const float4* Wp4 = (const float4*)g_Wp;
    auto stage2 = [&](int s, const float4* Ag, const float4* Bg) {
        cpa16(&A4[s * 512 + tid], Ag + tid);
        cpa16(&A4[s * 512 + tid + 256], Ag + tid + 256);
        cpa16(&B4[s * 512 + tid], Bg + tid);
        cpa16(&B4[s * 512 + tid + 256], Bg + tid + 256);
        CP_COMMIT();
    };

    for (int t = 0; t < NSTEP; t++) {
        const int cur = t & 1, old = cur ^ 1;
        if (tid < 64) xs[tid][0] = dts[(row0 + tid) * T_ + HIST + 1 + t];
        { const int r = tid >> 2, j = tid & 3;
          xs[r][10 + j] = acts[((row0 + r) * T_ + HIST + t) * 4 + j]; }
        __syncthreads();

        for (int l = 0; l < 8; l++) {
            float acc[4][4];
#pragma unroll
            for (int j = 0; j < 4; j++)
#pragma unroll
                for (int d = 0; d < 4; d++) acc[j][d] = 0.f;

            const float4* Bbase = Wp4 + (size_t)(l * 16 + bh) * 8192;
            const float4* Ah0 = (const float4*)&g_h[old][l][rg][0];

            if (l == 0) {
                stage2(0, Ah0, Bbase);
                stage2(1, Ah0 + 512, Bbase + 512);
                {   // x fragments
                    const int k8 = tid >> 7, wmx = (tid >> 5) & 3, ln = tid & 31;
                    const int gg = ln >> 2, tt = ln & 3;
                    float4 v;
                    v.x = tf32f(xs[wmx * 16 + gg][k8 * 8 + tt]);
                    v.y = tf32f(xs[wmx * 16 + gg + 8][k8 * 8 + tt]);
                    v.z = tf32f(xs[wmx * 16 + gg][k8 * 8 + tt + 4]);
                    v.w = tf32f(xs[wmx * 16 + gg + 8][k8 * 8 + tt + 4]);
                    AX[tid] = v;
                }
                __syncthreads();
#pragma unroll
                for (int k8 = 0; k8 < 2; k8++) {
                    float4 a  = AX[(k8 * 4 + wm) * 32 + lane];
                    float4 b0 = BX[((k8 * 2 + wn) * 2 + 0) * 32 + lane];
                    float4 b1 = BX[((k8 * 2 + wn) * 2 + 1) * 32 + lane];
                    mma8(acc[0], U(a.x), U(a.y), U(a.z), U(a.w), U(b0.x), U(b0.y));
                    mma8(acc[1], U(a.x), U(a.y), U(a.z), U(a.w), U(b0.z), U(b0.w));
                    mma8(acc[2], U(a.x), U(a.y), U(a.z), U(a.w), U(b1.x), U(b1.y));
                    mma8(acc[3], U(a.x), U(a.y), U(a.z), U(a.w), U(b1.z), U(b1.w));
                }
                for (int kc = 0; kc < 8; kc++) {
                    if (kc < 7) CP_WAIT(1); else CP_WAIT(0);
                    __syncthreads();
                    if (kc + 2 < 8) stage2((kc + 2) % 3, Ah0 + (kc + 2) * 512, Bbase + (kc + 2) * 512);
                    mma_frag(A4 + (kc % 3) * 512, B4 + (kc % 3) * 512, acc, wm, wn, lane);
                }
            } else {
                const float4* Ah1 = (const float4*)&g_h[cur][l - 1][rg][0];
                for (int kc = 0; kc < 16; kc++) {
                    if (kc < 15) CP_WAIT(1); else CP_WAIT(0);
                    __syncthreads();
                    if (kc == 6) {  // dependency on h[cur][l-1] before staging chunk 8
                        const unsigned tgt = (unsigned)(t * 8 + l);
                        if (tid < 16) {
                            while (((volatile unsigned*)g_prog)[rg * 16 + tid] < tgt) __nanosleep(32);
                            __threadfence();
                        }
                        __syncthreads();
                    }
                    if (kc + 2 < 16) {
                        const int c2 = kc + 2;
                        const float4* Ag = (c2 < 8) ? Ah0 + c2 * 512 : Ah1 + (c2 - 8) * 512;
                        stage2(c2 % 3, Ag, Bbase + c2 * 512);
                    }
                    mma_frag(A4 + (kc % 3) * 512, B4 + (kc % 3) * 512, acc, wm, wn, lane);
                }
            }

            __syncthreads();
            if (l < 7) {  // prefetch next layer's Whh chunks 0,1 (h_old ready)
                const float4* An = (const float4*)&g_h[old][l + 1][rg][0];
                const float4* Bn = Wp4 + (size_t)((l + 1) * 16 + bh) * 8192;
                stage2(0, An, Bn);
                stage2(1, An + 512, Bn + 512);
            }

            // register-only LSTM epilogue (gates = acc[0..3][d])
            float* hdst = &g_h[cur][l][rg][0];
#pragma unroll
            for (int d = 0; d < 4; d++) {
                const int r = wm * 16 + g + ((d & 2) ? 8 : 0);
                const int hc = wn * 8 + tq * 2 + (d & 1);
                const float iG = acc[0][d] + bias[l][hc];
                const float fG = acc[1][d] + bias[l][16 + hc];
                const float gG = acc[2][d] + bias[l][32 + hc];
                const float oG = acc[3][d] + bias[l][48 + hc];
                const float cn = sigf(fG) * c_reg[l][d] + sigf(iG) * tanhf_(gG);
                c_reg[l][d] = cn;
                const float hv = tf32f(sigf(oG) * tanhf_(cn));
                hdst[hfrag(r, hc0 + hc)] = hv;
                if (l == 7) g_h7row[rg][r][hc0 + hc] = hv;
            }
            __threadfence();
            __syncthreads();
            if (tid == 0)
                *(volatile unsigned*)&g_prog[rg * 16 + bh] = (unsigned)(t * 8 + l + 1);
        }

        // wait full step in this rowgroup
        if (tid < 16) {
            const unsigned tgt = (unsigned)(t * 8 + 8);
            while (((volatile unsigned*)g_prog)[rg * 16 + tid] < tgt) __nanosleep(32);
            __threadfence();
        }
        __syncthreads();

        // fc: 64 rows x 9 outs
        const int r1 = tid >> 3, o1 = tid & 7;
        float pa = __ldg(&bfc[o1]), pb = __ldg(&bfc[o1]);
        float pc = (tid < 64) ? __ldg(&bfc[8]) : 0.f;
        for (int qq = 0; qq < 4; qq++) {
            __syncthreads();
#pragma unroll
            for (int q = 0; q < 4; q++) {
                const int i = tid + 256 * q;
                const int r = i >> 4, kq = (i & 15) << 2;
                float4 v = __ldcg((const float4*)&g_h7row[rg][r][qq * 64 + kq]);
                Gs[r][kq] = v.x; Gs[r][kq + 1] = v.y; Gs[r][kq + 2] = v.z; Gs[r][kq + 3] = v.w;
            }
            __syncthreads();
#pragma unroll 4
            for (int k = 0; k < 64; k++) {
                const float w = __ldg(&Wfc[o1 * 256 + qq * 64 + k]);
                pa += Gs[r1][k] * w;
                pb += Gs[r1 + 32][k] * w;
                if (tid < 64) pc += Gs[tid][k] * __ldg(&Wfc[8 * 256 + qq * 64 + k]);
            }
        }
        __syncthreads();
        xs[r1][1 + o1] = pa;
        xs[r1 + 32][1 + o1] = pb;
        if (tid < 64) xs[tid][9] = pc;
        if (bh == 0) {
            out[(size_t)(row0 + r1) * (NSTEP * 9) + t * 9 + o1] = pa;
            out[(size_t)(row0 + r1 + 32) * (NSTEP * 9) + t * 9 + o1] = pb;
            if (tid < 64) out[(size_t)(row0 + tid) * (NSTEP * 9) + t * 9 + 8] = pc;
        }
        __syncthreads();
    }
}

extern "C" void kernel_launch(void* const* d_in, const int* in_sizes, int n_in,
                              void* d_out, int out_size) {
    const float* states = (const float*)d_in[0];
    const float* acts   = (const float*)d_in[1];
    const float* dts    = (const float*)d_in[2];
    const float* W1     = (const float*)d_in[3];
    const float* b1     = (const float*)d_in[4];
    const float* W2     = (const float*)d_in[5];
    const float* b2     = (const float*)d_in[6];
    const float* Wih0   = (const float*)d_in[7];
    const float* Whh0   = (const float*)d_in[8];
    const float* bih0   = (const float*)d_in[9];
    const float* bhh0   = (const float*)d_in[10];
    const float* Wih    = (const float*)d_in[11];
    const float* Whh    = (const float*)d_in[12];
    const float* bih    = (const float*)d_in[13];
    const float* bhh    = (const float*)d_in[14];
    const float* Wfc    = (const float*)d_in[15];
    const float* bfc    = (const float*)d_in[16];
    float* out = (float*)d_out;

    const int sm2 = 6 * 512 * 16;       // 49152
    const int smr = 20224 * 4;          // 80896
    cudaFuncSetAttribute(k_gemm2, cudaFuncAttributeMaxDynamicSharedMemorySize, sm2);
    cudaFuncSetAttribute(k_rollout, cudaFuncAttributeMaxDynamicSharedMemorySize, smr);

    k_prep_w<<<16384, 256>>>(Whh0, Wih, Whh);
    k_prep_w2<<<60032, 256>>>(W2);
    k_prep_small<<<81, 256>>>(Wih0);
    k_gemm1<<<16 * 118, 256>>>(states, acts, W1, b1);
    k_gemm2<<<512, 256, sm2>>>(b2);
    k_rollout<<<128, 256, smr>>>(states, acts, dts, bih0, bhh0,
                                 bih, bhh, Wfc, bfc, out);
}

// round 7
// speedup vs baseline: 1.1306x; 1.1306x over previous
#include <cuda_runtime.h>
#include <stdint.h>

#define B_    512
#define T_    76
#define HIST  10
#define H_    256
#define NSTEP 64
#define MLPH  15000
#define K1    130
#define NCH2  469
#define CHF   (NCH2 * 2048)

__device__ __align__(16) float g_mlpf[8][CHF];
__device__ __align__(16) float g_W2f[(size_t)64 * CHF];
__device__ __align__(16) float g_h[2][8][8][16384];
__device__ __align__(16) float g_h7row[8][64][256];
__device__ __align__(16) float g_c[8][B_][H_];
__device__ __align__(16) float g_Wp[4194304];   // [l][bh16][s2][kc8][2048]
__device__ __align__(16) float g_Wih0p[16][1024];
__device__ unsigned g_prog[128];

__device__ __forceinline__ float tf32f(float x) {
    uint32_t r; asm("cvt.rna.tf32.f32 %0, %1;" : "=r"(r) : "f"(x));
    return __uint_as_float(r);
}
#define U(x) __float_as_uint(x)
__device__ __forceinline__ void mma8(float c[4], uint32_t a0, uint32_t a1, uint32_t a2, uint32_t a3,
                                     uint32_t b0, uint32_t b1) {
    asm volatile("mma.sync.aligned.m16n8k8.row.col.f32.tf32.tf32.f32 "
                 "{%0,%1,%2,%3},{%4,%5,%6,%7},{%8,%9},{%0,%1,%2,%3};\n"
                 : "+f"(c[0]), "+f"(c[1]), "+f"(c[2]), "+f"(c[3])
                 : "r"(a0), "r"(a1), "r"(a2), "r"(a3), "r"(b0), "r"(b1));
}
__device__ __forceinline__ float sigf(float x) { return __fdividef(1.f, 1.f + __expf(-x)); }
__device__ __forceinline__ float tanhf_(float x) { return 2.f * sigf(2.f * x) - 1.f; }
__device__ __forceinline__ void cpa16(void* s, const void* g) {
    uint32_t sa = (uint32_t)__cvta_generic_to_shared(s);
    asm volatile("cp.async.cg.shared.global [%0], [%1], 16;" :: "r"(sa), "l"(g));
}
#define CP_COMMIT() asm volatile("cp.async.commit_group;\n")
#define CP_WAIT(n)  asm volatile("cp.async.wait_group %0;\n" :: "n"(n))

__device__ __forceinline__ int hfrag(int r, int k) {
    return ((((k >> 3) * 4 + (r >> 4)) * 32 + (r & 7) * 4 + (k & 3)) << 2)
           + ((r >> 3) & 1) + (((k >> 2) & 1) << 1);
}

__device__ __forceinline__ void mma_frag(const float4* Ac, const float4* Bc,
                                         float (&acc)[4][4], int wm, int wn, int lane) {
#pragma unroll
    for (int k8 = 0; k8 < 4; k8++) {
        float4 a  = Ac[(k8 * 4 + wm) * 32 + lane];
        float4 b0 = Bc[((k8 * 2 + wn) * 2 + 0) * 32 + lane];
        float4 b1 = Bc[((k8 * 2 + wn) * 2 + 1) * 32 + lane];
        mma8(acc[0], U(a.x), U(a.y), U(a.z), U(a.w), U(b0.x), U(b0.y));
        mma8(acc[1], U(a.x), U(a.y), U(a.z), U(a.w), U(b0.z), U(b0.w));
        mma8(acc[2], U(a.x), U(a.y), U(a.z), U(a.w), U(b1.x), U(b1.y));
        mma8(acc[3], U(a.x), U(a.y), U(a.z), U(a.w), U(b1.z), U(b1.w));
    }
}

// ---- prep: rollout weights, gate-interleaved fragments ----
__global__ void __launch_bounds__(256) k_prep_w(const float* __restrict__ Whh0,
                                                const float* __restrict__ Wih,
                                                const float* __restrict__ Whh) {
    const int idx = blockIdx.x * 256 + threadIdx.x;
    const int comp = idx & 3, c4 = (idx >> 2) & 511;
    const int lane = c4 & 31, half = (c4 >> 5) & 1, wn = (c4 >> 6) & 1, k8 = (c4 >> 7) & 3;
    const int kc = (idx >> 11) & 7, s = (idx >> 14) & 1, bh = (idx >> 15) & 15, l = (idx >> 19) & 7;
    const int gc = (wn * 4 + half * 2 + (comp >> 1)) * 8 + (lane >> 2);
    const int n = ((gc >> 3) & 3) * 256 + bh * 16 + (gc >> 5) * 8 + (gc & 7);
    const int k = kc * 32 + k8 * 8 + (comp & 1) * 4 + (lane & 3);
    float v = 0.f;
    if (l == 0) { if (s == 0) v = Whh0[n * 256 + k]; }
    else v = (s == 0) ? Whh[(size_t)(l - 1) * 262144 + n * 256 + k]
                      : Wih[(size_t)(l - 1) * 262144 + n * 256 + k];
    g_Wp[idx] = tf32f(v);
}

// ---- prep: W2 -> fragments via coalesced smem transpose ----
__global__ void __launch_bounds__(256) k_prep_w2t(const float* __restrict__ W2) {
    const int bn = blockIdx.x / NCH2, kc = blockIdx.x - bn * NCH2;
    const int tid = threadIdx.x;
    __shared__ float s[64][33];
#pragma unroll
    for (int q = 0; q < 2; q++) {
        const int f = tid + q * 256;
        const int n = f >> 3, kq = (f & 7) << 2;
        const int gk = kc * 32 + kq;
        float4 v;
        const float* p = W2 + (size_t)(bn * 64 + n) * MLPH;
        if (gk + 3 < MLPH) v = *(const float4*)(p + gk);
        else {
            v.x = (gk + 0 < MLPH) ? p[gk + 0] : 0.f;
            v.y = (gk + 1 < MLPH) ? p[gk + 1] : 0.f;
            v.z = (gk + 2 < MLPH) ? p[gk + 2] : 0.f;
            v.w = (gk + 3 < MLPH) ? p[gk + 3] : 0.f;
        }
        s[n][kq] = v.x; s[n][kq + 1] = v.y; s[n][kq + 2] = v.z; s[n][kq + 3] = v.w;
    }
    __syncthreads();
    float4* dst = ((float4*)g_W2f) + (size_t)(bn * NCH2 + kc) * 512;
#pragma unroll
    for (int q = 0; q < 2; q++) {
        const int j = tid + q * 256;
        const int lane = j & 31, half = (j >> 5) & 1, wn = (j >> 6) & 1, k8 = (j >> 7) & 3;
        float4 v; float* pv = (float*)&v;
#pragma unroll
        for (int c = 0; c < 4; c++) {
            const int gc = (wn * 4 + half * 2 + (c >> 1)) * 8 + (lane >> 2);
            const int k = k8 * 8 + (c & 1) * 4 + (lane & 3);
            pv[c] = tf32f(s[gc][k]);
        }
        dst[j] = v;
    }
}

__global__ void __launch_bounds__(256) k_prep_small(const float* __restrict__ Wih0) {
    const int i = blockIdx.x * 256 + threadIdx.x;
    if (i < 16384) {
        const int bh = i >> 10, pos = i & 1023;
        const int comp = pos & 3, c4 = pos >> 2;
        const int lane = c4 & 31, half = (c4 >> 5) & 1, wn = (c4 >> 6) & 1, k8 = (c4 >> 7) & 1;
        const int gc = (wn * 4 + half * 2 + (comp >> 1)) * 8 + (lane >> 2);
        const int n = ((gc >> 3) & 3) * 256 + bh * 16 + (gc >> 5) * 8 + (gc & 7);
        const int k = k8 * 8 + (comp & 1) * 4 + (lane & 3);
        g_Wih0p[bh][pos] = (k < 14) ? tf32f(Wih0[n * 14 + k]) : 0.f;
    } else if (i < 16384 + 4096) {
        const int j = i - 16384;
        const int rg = j >> 9, rem = j & 511;
        g_mlpf[rg][468 * 2048 + hfrag(rem >> 3, 24 + (rem & 7))] = 0.f;
    } else if (i < 16384 + 4096 + 128) {
        g_prog[i - 16384 - 4096] = 0u;
    }
}

// ---- GEMM1 ----
__global__ void __launch_bounds__(256) k_gemm1(const float* __restrict__ states,
                                               const float* __restrict__ acts,
                                               const float* __restrict__ W1,
                                               const float* __restrict__ b1) {
    const int bm = blockIdx.x & 15, bn = blockIdx.x >> 4, n0 = bn * 128;
    const int tid = threadIdx.x;
    __shared__ float enc_s[32][132];
    __shared__ float w_s[128][33];
    for (int i = tid; i < 32 * K1; i += 256) {
        const int r = i / K1, k = i % K1, b = bm * 32 + r;
        const int tt = k / 13, j = k % 13;
        enc_s[r][k] = (j < 9) ? states[(b * T_ + tt) * 12 + 3 + j]
                              : acts[(b * T_ + tt) * 4 + (j - 9)];
    }
    float acc[4][4];
#pragma unroll
    for (int a = 0; a < 4; a++)
#pragma unroll
        for (int b = 0; b < 4; b++) acc[a][b] = 0.f;
    const int tr = tid >> 5, tc = tid & 31;
    for (int k0 = 0; k0 < K1; k0 += 32) {
        const int kn = min(32, K1 - k0);
        __syncthreads();
        for (int i = tid; i < 4096; i += 256) {
            const int c = i >> 5, kk = i & 31, n = n0 + c;
            w_s[c][kk] = (kk < kn && n < MLPH) ? W1[n * K1 + k0 + kk] : 0.f;
        }
        __syncthreads();
        for (int kk = 0; kk < kn; kk++) {
            float a[4], w[4];
#pragma unroll
            for (int x = 0; x < 4; x++) a[x] = enc_s[tr + 8 * x][k0 + kk];
#pragma unroll
            for (int y = 0; y < 4; y++) w[y] = w_s[tc + 32 * y][kk];
#pragma unroll
            for (int x = 0; x < 4; x++)
#pragma unroll
                for (int y = 0; y < 4; y++) acc[x][y] += a[x] * w[y];
        }
    }
#pragma unroll
    for (int x = 0; x < 4; x++)
#pragma unroll
        for (int y = 0; y < 4; y++) {
            const int b = bm * 32 + tr + 8 * x, n = n0 + tc + 32 * y;
            if (n < MLPH)
                g_mlpf[b >> 6][(n >> 5) * 2048 + hfrag(b & 63, n & 31)] =
                    tf32f(fmaxf(acc[x][y] + b1[n], 0.f));
        }
}

// ---- GEMM2: fragment pipeline ----
__global__ void __launch_bounds__(256, 2) k_gemm2(const float* __restrict__ b2) {
    const int bm = blockIdx.x & 7, bn = blockIdx.x >> 3;
    const int tid = threadIdx.x;
    const int warp = tid >> 5, lane = tid & 31;
    const int wm = warp >> 1, wn = warp & 1;
    const int g = lane >> 2, tq = lane & 3;
    extern __shared__ __align__(16) float4 s4[];
    float4* A4 = s4; float4* B4 = s4 + 3 * 512;
    const float4* Asrc = (const float4*)g_mlpf[bm];
    const float4* Bsrc = ((const float4*)g_W2f) + (size_t)bn * (NCH2 * 512);

    float acc[4][4];
#pragma unroll
    for (int j = 0; j < 4; j++)
#pragma unroll
        for (int d = 0; d < 4; d++) acc[j][d] = 0.f;

    auto stage = [&](int s, int c) {
        cpa16(&A4[s * 512 + tid], Asrc + (size_t)c * 512 + tid);
        cpa16(&A4[s * 512 + tid + 256], Asrc + (size_t)c * 512 + tid + 256);
        cpa16(&B4[s * 512 + tid], Bsrc + (size_t)c * 512 + tid);
        cpa16(&B4[s * 512 + tid + 256], Bsrc + (size_t)c * 512 + tid + 256);
        CP_COMMIT();
    };
    stage(0, 0); stage(1, 1);
    for (int c = 0; c < NCH2; c++) {
        if (c < NCH2 - 1) CP_WAIT(1); else CP_WAIT(0);
        __syncthreads();
        if (c + 2 < NCH2) stage((c + 2) % 3, c + 2);
        mma_frag(A4 + (c % 3) * 512, B4 + (c % 3) * 512, acc, wm, wn, lane);
    }
#pragma unroll
    for (int j = 0; j < 4; j++)
#pragma unroll
        for (int d = 0; d < 4; d++) {
            const int r = wm * 16 + g + ((d & 2) ? 8 : 0);
            const int p = (wn * 4 + j) * 8 + tq * 2 + (d & 1);
            const int n = bn * 64 + p;
            const float v = acc[j][d] + b2[n];
            const int l = n >> 9, rem = n & 511;
            if (rem < H_) g_h[1][l][bm][hfrag(r, rem)] = tf32f(v);
            else          g_c[l][bm * 64 + r][rem - H_] = v;
        }
}

// ---- rollout: two-pass, 64k chunks, register epilogue ----
__global__ void __launch_bounds__(256) k_rollout(
    const float* __restrict__ states, const float* __restrict__ acts,
    const float* __restrict__ dts,
    const float* __restrict__ bih0, const float* __restrict__ bhh0,
    const float* __restrict__ bih, const float* __restrict__ bhh,
    const float* __restrict__ Wfc, const float* __restrict__ bfc,
    float* __restrict__ out)
{
    const int rg = blockIdx.x >> 4, bh = blockIdx.x & 15;
    const int tid = threadIdx.x;
    const int warp = tid >> 5, lane = tid & 31;
    const int wm = warp >> 1, wn = warp & 1;
    const int g = lane >> 2, tq = lane & 3;
    const int row0 = rg * 64, hc0 = bh * 16;

    extern __shared__ __align__(16) float sm[];
    float4* A4 = (float4*)sm;                    // 3*1024 f4
    float4* B4 = (float4*)(sm + 12288);          // 3*1024 f4
    float4* AX = (float4*)(sm + 24576);          // 256 f4
    float4* BX = (float4*)(sm + 25600);          // 256 f4
    float (*Gs)[68]   = (float(*)[68])(sm + 26624);
    float (*xs)[16]   = (float(*)[16])(sm + 30976);
    float (*bias)[64] = (float(*)[64])(sm + 32000);

    cpa16(&BX[tid], &((const float4*)g_Wih0p[bh])[tid]);
    CP_COMMIT();

    for (int i = tid; i < 512; i += 256) {
        const int l = i >> 6, gc = i & 63;
        const int n = (gc >> 4) * 256 + hc0 + (gc & 15);
        bias[l][gc] = (l == 0) ? __ldg(&bih0[n]) + __ldg(&bhh0[n])
                               : __ldg(&bih[(l - 1) * 1024 + n]) + __ldg(&bhh[(l - 1) * 1024 + n]);
    }
    float c_reg[8][4];
#pragma unroll
    for (int l = 0; l < 8; l++)
#pragma unroll
        for (int d = 0; d < 4; d++) {
            const int r = wm * 16 + g + ((d & 2) ? 8 : 0);
            const int hc = wn * 8 + tq * 2 + (d & 1);
            c_reg[l][d] = __ldcg(&g_c[l][row0 + r][hc0 + hc]);
        }
    for (int i = tid; i < 576; i += 256) {
        const int r = i / 9, j = i % 9;
        xs[r][1 + j] = states[((row0 + r) * T_ + HIST) * 12 + 3 + j];
    }
    if (tid < 128) xs[tid >> 1][14 + (tid & 1)] = 0.f;
    CP_WAIT(0);
    __syncthreads();

    const float4* Wp4 = (const float4*)g_Wp;
    auto stage64 = [&](int s, const float4* Ag, const float4* Bg) {
#pragma unroll
        for (int q = 0; q < 4; q++) {
            cpa16(&A4[s * 1024 + tid + q * 256], Ag + tid + q * 256);
            cpa16(&B4[s * 1024 + tid + q * 256], Bg + tid + q * 256);
        }
        CP_COMMIT();
    };
    auto pass4 = [&](const float4* Ah, const float4* Bb, float (&acc)[4][4]) {
        stage64(0, Ah, Bb);
        stage64(1, Ah + 1024, Bb + 1024);
        for (int j = 0; j < 4; j++) {
            if (j < 3) CP_WAIT(1); else CP_WAIT(0);
            __syncthreads();
            if (j + 2 < 4) stage64((j + 2) % 3, Ah + (j + 2) * 1024, Bb + (j + 2) * 1024);
            mma_frag(A4 + (j % 3) * 1024,       B4 + (j % 3) * 1024,       acc, wm, wn, lane);
            mma_frag(A4 + (j % 3) * 1024 + 512, B4 + (j % 3) * 1024 + 512, acc, wm, wn, lane);
            __syncthreads();
        }
    };

    for (int t = 0; t < NSTEP; t++) {
        const int cur = t & 1, old = cur ^ 1;
        if (tid < 64) xs[tid][0] = dts[(row0 + tid) * T_ + HIST + 1 + t];
        { const int r = tid >> 2, j = tid & 3;
          xs[r][10 + j] = acts[((row0 + r) * T_ + HIST + t) * 4 + j]; }
        __syncthreads();

        for (int l = 0; l < 8; l++) {
            float acc[4][4];
#pragma unroll
            for (int j = 0; j < 4; j++)
#pragma unroll
                for (int d = 0; d < 4; d++) acc[j][d] = 0.f;

            const float4* Bb = Wp4 + (size_t)(l * 16 + bh) * 8192;
            const float4* Ah0 = (const float4*)&g_h[old][l][rg][0];

            if (l == 0) {
                {   // x fragments
                    const int k8 = tid >> 7, wmx = (tid >> 5) & 3, ln = tid & 31;
                    const int gg = ln >> 2, tt = ln & 3;
                    float4 v;
                    v.x = tf32f(xs[wmx * 16 + gg][k8 * 8 + tt]);
                    v.y = tf32f(xs[wmx * 16 + gg + 8][k8 * 8 + tt]);
                    v.z = tf32f(xs[wmx * 16 + gg][k8 * 8 + tt + 4]);
                    v.w = tf32f(xs[wmx * 16 + gg + 8][k8 * 8 + tt + 4]);
                    AX[tid] = v;
                }
                __syncthreads();
#pragma unroll
                for (int k8 = 0; k8 < 2; k8++) {
                    float4 a  = AX[(k8 * 4 + wm) * 32 + lane];
                    float4 b0 = BX[((k8 * 2 + wn) * 2 + 0) * 32 + lane];
                    float4 b1 = BX[((k8 * 2 + wn) * 2 + 1) * 32 + lane];
                    mma8(acc[0], U(a.x), U(a.y), U(a.z), U(a.w), U(b0.x), U(b0.y));
                    mma8(acc[1], U(a.x), U(a.y), U(a.z), U(a.w), U(b0.z), U(b0.w));
                    mma8(acc[2], U(a.x), U(a.y), U(a.z), U(a.w), U(b1.x), U(b1.y));
                    mma8(acc[3], U(a.x), U(a.y), U(a.z), U(a.w), U(b1.z), U(b1.w));
                }
                pass4(Ah0, Bb, acc);
            } else {
                pass4(Ah0, Bb, acc);            // Whh on h_old — no dependency
                const unsigned tgt = (unsigned)(t * 8 + l);
                if (tid < 16) {
                    while (((volatile unsigned*)g_prog)[rg * 16 + tid] < tgt) __nanosleep(32);
                    __threadfence();
                }
                __syncthreads();
                pass4((const float4*)&g_h[cur][l - 1][rg][0], Bb + 4096, acc);
            }

            // register LSTM epilogue
            float* hdst = &g_h[cur][l][rg][0];
#pragma unroll
            for (int d = 0; d < 4; d++) {
                const int r = wm * 16 + g + ((d & 2) ? 8 : 0);
                const int hc = wn * 8 + tq * 2 + (d & 1);
                const float iG = acc[0][d] + bias[l][hc];
                const float fG = acc[1][d] + bias[l][16 + hc];
                const float gG = acc[2][d] + bias[l][32 + hc];
                const float oG = acc[3][d] + bias[l][48 + hc];
                const float cn = sigf(fG) * c_reg[l][d] + sigf(iG) * tanhf_(gG);
                c_reg[l][d] = cn;
                const float hv = tf32f(sigf(oG) * tanhf_(cn));
                hdst[hfrag(r, hc0 + hc)] = hv;
                if (l == 7) g_h7row[rg][r][hc0 + hc] = hv;
            }
            __threadfence();
            __syncthreads();
            if (tid == 0)
                *(volatile unsigned*)&g_prog[rg * 16 + bh] = (unsigned)(t * 8 + l + 1);
        }

        if (tid < 16) {
            const unsigned tgt = (unsigned)(t * 8 + 8);
            while (((volatile unsigned*)g_prog)[rg * 16 + tid] < tgt) __nanosleep(32);
            __threadfence();
        }
        __syncthreads();

        // fc
        const int r1 = tid >> 3, o1 = tid & 7;
        float pa = __ldg(&bfc[o1]), pb = __ldg(&bfc[o1]);
        float pc = (tid < 64) ? __ldg(&bfc[8]) : 0.f;
        for (int qq = 0; qq < 4; qq++) {
            __syncthreads();
#pragma unroll
            for (int q = 0; q < 4; q++) {
                const int i = tid + 256 * q;
                const int r = i >> 4, kq = (i & 15) << 2;
                float4 v = __ldcg((const float4*)&g_h7row[rg][r][qq * 64 + kq]);
                Gs[r][kq] = v.x; Gs[r][kq + 1] = v.y; Gs[r][kq + 2] = v.z; Gs[r][kq + 3] = v.w;
            }
            __syncthreads();
#pragma unroll 4
            for (int k = 0; k < 64; k++) {
                const float w = __ldg(&Wfc[o1 * 256 + qq * 64 + k]);
                pa += Gs[r1][k] * w;
                pb += Gs[r1 + 32][k] * w;
                if (tid < 64) pc += Gs[tid][k] * __ldg(&Wfc[8 * 256 + qq * 64 + k]);
            }
        }
        __syncthreads();
        xs[r1][1 + o1] = pa;
        xs[r1 + 32][1 + o1] = pb;
        if (tid < 64) xs[tid][9] = pc;
        if (bh == 0) {
            out[(size_t)(row0 + r1) * (NSTEP * 9) + t * 9 + o1] = pa;
            out[(size_t)(row0 + r1 + 32) * (NSTEP * 9) + t * 9 + o1] = pb;
            if (tid < 64) out[(size_t)(row0 + tid) * (NSTEP * 9) + t * 9 + 8] = pc;
        }
        __syncthreads();
    }
}

extern "C" void kernel_launch(void* const* d_in, const int* in_sizes, int n_in,
                              void* d_out, int out_size) {
    const float* states = (const float*)d_in[0];
    const float* acts   = (const float*)d_in[1];
    const float* dts    = (const float*)d_in[2];
    const float* W1     = (const float*)d_in[3];
    const float* b1     = (const float*)d_in[4];
    const float* W2     = (const float*)d_in[5];
    const float* b2     = (const float*)d_in[6];
    const float* Wih0   = (const float*)d_in[7];
    const float* Whh0   = (const float*)d_in[8];
    const float* bih0   = (const float*)d_in[9];
    const float* bhh0   = (const float*)d_in[10];
    const float* Wih    = (const float*)d_in[11];
    const float* Whh    = (const float*)d_in[12];
    const float* bih    = (const float*)d_in[13];
    const float* bhh    = (const float*)d_in[14];
    const float* Wfc    = (const float*)d_in[15];
    const float* bfc    = (const float*)d_in[16];
    float* out = (float*)d_out;

    const int sm2 = 6 * 512 * 16;       // 49152
    const int smr = 32512 * 4;          // 130048
    cudaFuncSetAttribute(k_gemm2, cudaFuncAttributeMaxDynamicSharedMemorySize, sm2);
    cudaFuncSetAttribute(k_rollout, cudaFuncAttributeMaxDynamicSharedMemorySize, smr);

    k_prep_w<<<16384, 256>>>(Whh0, Wih, Whh);
    k_prep_w2t<<<64 * NCH2, 256>>>(W2);
    k_prep_small<<<81, 256>>>(Wih0);
    k_gemm1<<<16 * 118, 256>>>(states, acts, W1, b1);
    k_gemm2<<<512, 256, sm2>>>(b2);
    k_rollout<<<128, 256, smr>>>(states, acts, dts, bih0, bhh0,
                                 bih, bhh, Wfc, bfc, out);
}